// round 10
// baseline (speedup 1.0000x reference)
#include <cuda_runtime.h>
#include <cstdint>
#include <cstddef>

#define KDIM 512
#define NRE 257
#define NTOT 514
#define NPAD 576
#define BM 128
#define BK 32
#define STAGES 4
#define THREADS 256
#define A_STAGE_BYTES (BM * BK * 4)                 // 16384
#define SMEM_BYTES (STAGES * A_STAGE_BYTES)         // 65536
#define STG_STRIDE 100

// Pre-converted, zero-padded, k-pair-permuted B (tf32 bits).
// Row n, k8 group: order [k0,k4,k1,k5,k2,k6,k3,k7] -> thread t's fragment (k_t,k_{t+4}) is 8B.
__device__ uint32_t g_Bcvt[NPAD * KDIM];

__device__ __forceinline__ void mma_tf32(float& c0, float& c1, float& c2, float& c3,
                                         uint32_t a0, uint32_t a1, uint32_t a2, uint32_t a3,
                                         uint32_t b0, uint32_t b1) {
    asm volatile(
        "mma.sync.aligned.m16n8k8.row.col.f32.tf32.tf32.f32 "
        "{%0,%1,%2,%3}, {%4,%5,%6,%7}, {%8,%9}, {%0,%1,%2,%3};\n"
        : "+f"(c0), "+f"(c1), "+f"(c2), "+f"(c3)
        : "r"(a0), "r"(a1), "r"(a2), "r"(a3), "r"(b0), "r"(b1));
}

__device__ __forceinline__ uint32_t f2tf32(float f) {
    uint32_t r;
    asm volatile("cvt.rna.tf32.f32 %0, %1;\n" : "=r"(r) : "f"(f));
    return r;
}

__device__ __forceinline__ uint32_t f2tf32_u(uint32_t fbits) {
    uint32_t r;
    asm volatile("cvt.rna.tf32.f32 %0, %1;\n" : "=r"(r) : "r"(fbits));
    return r;
}

__device__ __forceinline__ void cpa16(uint32_t dst, const void* src) {
    asm volatile("cp.async.cg.shared.global [%0], [%1], 16;" :: "r"(dst), "l"(src));
}

template <int N>
__device__ __forceinline__ void cpa_wait() {
    asm volatile("cp.async.wait_group %0;" :: "n"(N) : "memory");
}

// ---- pre-kernel: padded, permuted tf32 B ----
__global__ void build_B_kernel(const float* __restrict__ MR, const float* __restrict__ MI) {
    int idx = blockIdx.x * blockDim.x + threadIdx.x;   // 0 .. NPAD*KDIM-1
    int n = idx >> 9;
    int k = idx & 511;
    float v = 0.f;
    if (n < NRE)       v = MR[(size_t)n * KDIM + k];
    else if (n < NTOT) v = MI[(size_t)(n - NRE) * KDIM + k];
    int p = (k & ~7) | (((k & 3) << 1) | ((k >> 2) & 1));   // pair-permute within k8 group
    g_Bcvt[(size_t)n * KDIM + p] = f2tf32(v);
}

// Cooperative A stage load: 128 rows x 32 fp32, 16B-chunk swizzle ch ^ (row&7).
__device__ __forceinline__ void load_A(const float* __restrict__ X, uint32_t smem_u32,
                                       int m0, int tid, int kt, int stage) {
    const uint32_t abase = smem_u32 + stage * A_STAGE_BYTES;
#pragma unroll
    for (int i = 0; i < 4; i++) {
        int idx = tid + i * THREADS;      // 0..1023
        int row = idx >> 3;               // 0..127
        int ch  = idx & 7;
        uint32_t dst = abase + row * 128 + ((ch * 16) ^ ((row & 7) * 16));
        cpa16(dst, X + (size_t)(m0 + row) * KDIM + kt * BK + ch * 4);
    }
    asm volatile("cp.async.commit_group;" ::: "memory");
}

template <int NB>   // warp handles 32 x (NB*8) output; CTA N width = 2*NB*8
__device__ __forceinline__ void gemm_path(const float* __restrict__ X,
                                          float* __restrict__ OUT, int M,
                                          int m0, int n0, char* smem) {
    uint32_t* Ssm = (uint32_t*)smem;
    const int tid = threadIdx.x;
    const int w = tid >> 5;
    const int lane = tid & 31;
    const int wm = w >> 1;            // 0..3 : 32-row M slice
    const int wn = w & 1;             // 0..1 : NB*8-col N slice
    const int g = lane >> 2;
    const int t = lane & 3;
    const uint32_t smem_u32 = (uint32_t)__cvta_generic_to_shared(smem);

#pragma unroll
    for (int p = 0; p < STAGES; p++)
        load_A(X, smem_u32, m0, tid, p, p);

    float acc[2][NB][4];
#pragma unroll
    for (int mb = 0; mb < 2; mb++)
#pragma unroll
        for (int nb = 0; nb < NB; nb++)
#pragma unroll
            for (int j = 0; j < 4; j++)
                acc[mb][nb][j] = 0.f;

    const int gsw = g << 2;
    int aOff[2];
#pragma unroll
    for (int mb = 0; mb < 2; mb++)
        aOff[mb] = (wm * 32 + mb * 16 + g) * 32;

    // per-thread B gmem base: row (n0 + wn*NB*8 + g), element t*2 of each permuted k8 group
    const uint32_t* Bp = g_Bcvt + (size_t)(n0 + wn * NB * 8 + g) * KDIM + t * 2;

#pragma unroll 1
    for (int kt = 0; kt < KDIM / BK; kt++) {
        if (kt < 13)       cpa_wait<3>();
        else if (kt == 13) cpa_wait<2>();
        else if (kt == 14) cpa_wait<1>();
        else               cpa_wait<0>();
        __syncthreads();

        const uint32_t* sp = Ssm + (kt & 3) * (A_STAGE_BYTES / 4);
        const uint32_t* bkt = Bp + kt * BK;
#pragma unroll
        for (int ks = 0; ks < 4; ks++) {
            const int c0 = (ks * 8 + t) ^ gsw;
            const int c1 = c0 ^ 4;
            uint32_t b[NB][2];
#pragma unroll
            for (int nb = 0; nb < NB; nb++) {
                uint2 v = __ldg((const uint2*)(bkt + nb * 8 * KDIM + ks * 8));
                b[nb][0] = v.x;
                b[nb][1] = v.y;
            }
#pragma unroll
            for (int mb = 0; mb < 2; mb++) {
                const uint32_t* ap = sp + aOff[mb];
                uint32_t a0 = f2tf32_u(ap[c0]);
                uint32_t a1 = f2tf32_u(ap[c0 + 256]);   // row + 8
                uint32_t a2 = f2tf32_u(ap[c1]);
                uint32_t a3 = f2tf32_u(ap[c1 + 256]);
#pragma unroll
                for (int nb = 0; nb < NB; nb++)
                    mma_tf32(acc[mb][nb][0], acc[mb][nb][1], acc[mb][nb][2], acc[mb][nb][3],
                             a0, a1, a2, a3, b[nb][0], b[nb][1]);
            }
        }

        __syncthreads();
        if (kt + STAGES < KDIM / BK)
            load_A(X, smem_u32, m0, tid, kt + STAGES, kt & 3);
    }

    // ---- epilogue: smem-staged, coalesced stores ----
    __syncthreads();
    float* stg = (float*)smem;     // 128 x STG_STRIDE floats = 51.2 KB < 64 KB
#pragma unroll
    for (int mb = 0; mb < 2; mb++) {
#pragma unroll
        for (int nb = 0; nb < NB; nb++) {
            const int row = wm * 32 + mb * 16 + g;
            const int col = wn * NB * 8 + nb * 8 + 2 * t;
            stg[row * STG_STRIDE + col]           = acc[mb][nb][0];
            stg[row * STG_STRIDE + col + 1]       = acc[mb][nb][1];
            stg[(row + 8) * STG_STRIDE + col]     = acc[mb][nb][2];
            stg[(row + 8) * STG_STRIDE + col + 1] = acc[mb][nb][3];
        }
    }
    __syncthreads();

    float* re = OUT;
    float* im = OUT + (size_t)M * NRE;
    const int NCOLS = 2 * NB * 8;   // 96 or 48
#pragma unroll
    for (int rr = 0; rr < 16; rr++) {
        const int row = w * 16 + rr;
        const size_t r = m0 + row;
#pragma unroll
        for (int c = 0; c < (NCOLS + 31) / 32; c++) {
            const int cl = c * 32 + lane;
            if (cl < NCOLS) {
                const int n = n0 + cl;
                const float v = stg[row * STG_STRIDE + cl];
                if (n < NRE)       re[r * NRE + n] = v;
                else if (n < NTOT) im[r * NRE + (n - NRE)] = v;
            }
        }
    }
}

__global__ void __launch_bounds__(THREADS, 2)
rfft_wmma_kernel(const float* __restrict__ X, float* __restrict__ OUT, int M) {
    extern __shared__ __align__(1024) char smem[];
    const int m0 = blockIdx.y * BM;
    if (blockIdx.x < 5) {
        gemm_path<6>(X, OUT, M, m0, blockIdx.x * 96, smem);   // n 0..479 (all real)
    } else {
        gemm_path<3>(X, OUT, M, m0, 480, smem);               // n 480..527 (covers 480..513)
    }
}

extern "C" void kernel_launch(void* const* d_in, const int* in_sizes, int n_in,
                              void* d_out, int out_size) {
    const float* X  = (const float*)d_in[0];
    const float* MR = (const float*)d_in[1];
    const float* MI = (const float*)d_in[2];
    float* OUT = (float*)d_out;
    const int M = in_sizes[0] / KDIM;   // 128000

    build_B_kernel<<<(NPAD * KDIM) / 256, 256>>>(MR, MI);

    cudaFuncSetAttribute(rfft_wmma_kernel, cudaFuncAttributeMaxDynamicSharedMemorySize, SMEM_BYTES);
    dim3 grid(6, M / BM);   // 5 full columns + 1 tail column
    rfft_wmma_kernel<<<grid, THREADS, SMEM_BYTES>>>(X, OUT, M);
}

// round 12
// speedup vs baseline: 1.7436x; 1.7436x over previous
#include <cuda_runtime.h>
#include <cstdint>
#include <cstddef>

#define KDIM 512
#define NRE 257
#define NTOT 514
#define NPAD 576
#define BM 128
#define BK 32
#define STAGES 3
#define THREADS 256
#define A_STAGE_BYTES (BM * BK * 4)                 // 16384
#define B_STAGE_BYTES_MAX (96 * BK * 4)             // 12288 (NB=6 path)
#define STAGE_BYTES_MAX (A_STAGE_BYTES + B_STAGE_BYTES_MAX)
#define SMEM_BYTES (STAGES * STAGE_BYTES_MAX)       // 86016
#define STG_STRIDE 100

// Pre-converted, zero-padded, k-pair-permuted B (tf32 bits).
// Row n, k8 group: order [k0,k4,k1,k5,k2,k6,k3,k7] so thread t's pair (k_t, k_{t+4}) is 8B.
__device__ uint32_t g_Bcvt[NPAD * KDIM];

__device__ __forceinline__ void mma_tf32(float& c0, float& c1, float& c2, float& c3,
                                         uint32_t a0, uint32_t a1, uint32_t a2, uint32_t a3,
                                         uint32_t b0, uint32_t b1) {
    asm volatile(
        "mma.sync.aligned.m16n8k8.row.col.f32.tf32.tf32.f32 "
        "{%0,%1,%2,%3}, {%4,%5,%6,%7}, {%8,%9}, {%0,%1,%2,%3};\n"
        : "+f"(c0), "+f"(c1), "+f"(c2), "+f"(c3)
        : "r"(a0), "r"(a1), "r"(a2), "r"(a3), "r"(b0), "r"(b1));
}

__device__ __forceinline__ uint32_t f2tf32(float f) {
    uint32_t r;
    asm volatile("cvt.rna.tf32.f32 %0, %1;\n" : "=r"(r) : "f"(f));
    return r;
}

__device__ __forceinline__ uint32_t f2tf32_u(uint32_t fbits) {
    uint32_t r;
    asm volatile("cvt.rna.tf32.f32 %0, %1;\n" : "=r"(r) : "r"(fbits));
    return r;
}

__device__ __forceinline__ void cpa16(uint32_t dst, const void* src) {
    asm volatile("cp.async.cg.shared.global [%0], [%1], 16;" :: "r"(dst), "l"(src));
}

template <int N>
__device__ __forceinline__ void cpa_wait() {
    asm volatile("cp.async.wait_group %0;" :: "n"(N) : "memory");
}

// ---- pre-kernel: padded, permuted tf32 B ----
__global__ void build_B_kernel(const float* __restrict__ MR, const float* __restrict__ MI) {
    int idx = blockIdx.x * blockDim.x + threadIdx.x;   // 0 .. NPAD*KDIM-1
    int n = idx >> 9;
    int k = idx & 511;
    float v = 0.f;
    if (n < NRE)       v = MR[(size_t)n * KDIM + k];
    else if (n < NTOT) v = MI[(size_t)(n - NRE) * KDIM + k];
    int p = (k & ~7) | (((k & 3) << 1) | ((k >> 2) & 1));   // pair-permute within k8 group
    g_Bcvt[(size_t)n * KDIM + p] = f2tf32(v);
}

template <int NB>   // warp tile 32 x (NB*8); CTA N width = 2*NB*8
__device__ __forceinline__ void gemm_path(const float* __restrict__ X,
                                          float* __restrict__ OUT, int M,
                                          int m0, int n0, char* smem) {
    constexpr int BROWS = 2 * NB * 8;                       // 96 or 48
    constexpr int B_STAGE_BYTES = BROWS * BK * 4;
    constexpr int STAGE_BYTES = A_STAGE_BYTES + B_STAGE_BYTES;
    constexpr int B_OFF32 = A_STAGE_BYTES / 4;

    uint32_t* Ssm = (uint32_t*)smem;
    const int tid = threadIdx.x;
    const int w = tid >> 5;
    const int lane = tid & 31;
    const int wm = w >> 1;            // 0..3 : 32-row M slice
    const int wn = w & 1;             // 0..1 : NB*8-col N slice
    const int g = lane >> 2;
    const int t = lane & 3;
    const uint32_t smem_u32 = (uint32_t)__cvta_generic_to_shared(smem);

    // ---- stage loader (A + B cooperative cp.async) ----
    auto load_stage = [&](int kt, int stage) {
        const uint32_t abase = smem_u32 + stage * STAGE_BYTES;
#pragma unroll
        for (int i = 0; i < 4; i++) {
            int idx = tid + i * THREADS;      // 0..1023
            int row = idx >> 3;               // 0..127
            int ch  = idx & 7;
            uint32_t dst = abase + row * 128 + ((ch * 16) ^ ((row & 7) * 16));
            cpa16(dst, X + (size_t)(m0 + row) * KDIM + kt * BK + ch * 4);
        }
        const uint32_t bbase = abase + A_STAGE_BYTES;
#pragma unroll
        for (int i = 0; i < (BROWS * 8 + THREADS - 1) / THREADS; i++) {
            int idx = tid + i * THREADS;
            if (idx < BROWS * 8) {
                int row = idx >> 3;
                int ch  = idx & 7;
                int win = ch >> 1, half = ch & 1;
                uint32_t dst = bbase + row * 128 + (((win + row) & 3) << 5) + (half << 4);
                cpa16(dst, g_Bcvt + (size_t)(n0 + row) * KDIM + kt * BK + ch * 4);
            }
        }
        asm volatile("cp.async.commit_group;" ::: "memory");
    };

#pragma unroll
    for (int p = 0; p < STAGES; p++)
        load_stage(p, p);

    float acc[2][NB][4];
#pragma unroll
    for (int mb = 0; mb < 2; mb++)
#pragma unroll
        for (int nb = 0; nb < NB; nb++)
#pragma unroll
            for (int j = 0; j < 4; j++)
                acc[mb][nb][j] = 0.f;

    const int gsw = g << 2;
    int aOff[2];
#pragma unroll
    for (int mb = 0; mb < 2; mb++)
        aOff[mb] = (wm * 32 + mb * 16 + g) * 32;
    const int bBase = B_OFF32 + (wn * NB * 8 + g) * 32 + t * 2;   // + nb*256 immediate
    const int rot = g & 3;    // (wn*NB*8 + nb*8 + g) & 3 == g & 3  (all terms mult of 4 except g)

#pragma unroll 1
    for (int kt = 0; kt < KDIM / BK; kt++) {
        if (kt < 14)       cpa_wait<2>();
        else if (kt == 14) cpa_wait<1>();
        else               cpa_wait<0>();
        __syncthreads();

        const uint32_t* sp = Ssm + (kt % STAGES) * (STAGE_BYTES / 4);
#pragma unroll
        for (int ks = 0; ks < 4; ks++) {
            const int c0 = (ks * 8 + t) ^ gsw;
            const int c1 = c0 ^ 4;
            const int woff = ((ks + rot) & 3) << 3;
            uint32_t b[NB][2];
#pragma unroll
            for (int nb = 0; nb < NB; nb++) {
                uint2 v = *(const uint2*)(sp + bBase + nb * 256 + woff);
                b[nb][0] = v.x;
                b[nb][1] = v.y;
            }
#pragma unroll
            for (int mb = 0; mb < 2; mb++) {
                const uint32_t* ap = sp + aOff[mb];
                uint32_t a0 = f2tf32_u(ap[c0]);
                uint32_t a1 = f2tf32_u(ap[c0 + 256]);   // row + 8
                uint32_t a2 = f2tf32_u(ap[c1]);
                uint32_t a3 = f2tf32_u(ap[c1 + 256]);
#pragma unroll
                for (int nb = 0; nb < NB; nb++)
                    mma_tf32(acc[mb][nb][0], acc[mb][nb][1], acc[mb][nb][2], acc[mb][nb][3],
                             a0, a1, a2, a3, b[nb][0], b[nb][1]);
            }
        }

        __syncthreads();
        if (kt + STAGES < KDIM / BK)
            load_stage(kt + STAGES, kt % STAGES);
    }

    // ---- epilogue: smem-staged, coalesced stores ----
    __syncthreads();
    float* stg = (float*)smem;     // 128 x STG_STRIDE floats = 51.2 KB
#pragma unroll
    for (int mb = 0; mb < 2; mb++) {
#pragma unroll
        for (int nb = 0; nb < NB; nb++) {
            const int row = wm * 32 + mb * 16 + g;
            const int col = wn * NB * 8 + nb * 8 + 2 * t;
            stg[row * STG_STRIDE + col]           = acc[mb][nb][0];
            stg[row * STG_STRIDE + col + 1]       = acc[mb][nb][1];
            stg[(row + 8) * STG_STRIDE + col]     = acc[mb][nb][2];
            stg[(row + 8) * STG_STRIDE + col + 1] = acc[mb][nb][3];
        }
    }
    __syncthreads();

    float* re = OUT;
    float* im = OUT + (size_t)M * NRE;
#pragma unroll
    for (int rr = 0; rr < 16; rr++) {
        const int row = w * 16 + rr;
        const size_t r = m0 + row;
#pragma unroll
        for (int c = 0; c < BROWS / 32 + (BROWS % 32 ? 1 : 0); c++) {
            const int cl = c * 32 + lane;
            if (cl < BROWS) {
                const int n = n0 + cl;
                const float v = stg[row * STG_STRIDE + cl];
                if (n < NRE)       re[r * NRE + n] = v;
                else if (n < NTOT) im[r * NRE + (n - NRE)] = v;
            }
        }
    }
}

__global__ void __launch_bounds__(THREADS, 2)
rfft_wmma_kernel(const float* __restrict__ X, float* __restrict__ OUT, int M) {
    extern __shared__ __align__(1024) char smem[];
    const int m0 = blockIdx.y * BM;
    if (blockIdx.x < 5) {
        gemm_path<6>(X, OUT, M, m0, blockIdx.x * 96, smem);   // n 0..479 (all real)
    } else {
        gemm_path<3>(X, OUT, M, m0, 480, smem);               // n 480..527 (covers 480..513)
    }
}

extern "C" void kernel_launch(void* const* d_in, const int* in_sizes, int n_in,
                              void* d_out, int out_size) {
    const float* X  = (const float*)d_in[0];
    const float* MR = (const float*)d_in[1];
    const float* MI = (const float*)d_in[2];
    float* OUT = (float*)d_out;
    const int M = in_sizes[0] / KDIM;   // 128000

    build_B_kernel<<<(NPAD * KDIM) / 256, 256>>>(MR, MI);

    cudaFuncSetAttribute(rfft_wmma_kernel, cudaFuncAttributeMaxDynamicSharedMemorySize, SMEM_BYTES);
    dim3 grid(6, M / BM);   // 5 full 96-wide columns + 1 48-wide tail
    rfft_wmma_kernel<<<grid, THREADS, SMEM_BYTES>>>(X, OUT, M);
}